// round 15
// baseline (speedup 1.0000x reference)
#include <cuda_runtime.h>
#include <cuda_bf16.h>
#include <cstdint>
#include <math.h>

#define DIM     2048
#define NEXP    64
#define NTOK    16384
#define BM      64
#define KC      128           // K per chunk
#define NCHUNK  (DIM / KC)    // 16
#define BROWB   272           // bf16 B row: 256B data + 16B pad (conflict-free ldmatrix)
#define SPLIT_B 17408         // 64 rows * 272B
#define STAGE_B 34816         // hi + lo
#define OBH(s)  ((s) * STAGE_B)
#define OBL(s)  ((s) * STAGE_B + SPLIT_B)
#define SMEM_SZ (3 * STAGE_B) // 104448
#define TAU 1e-4f

__device__ unsigned short g_WtHi[NEXP * DIM];
__device__ unsigned short g_WtLo[NEXP * DIM];

// ---------- helpers ----------
__device__ __forceinline__ uint32_t smem_u32(const void* p) {
    uint32_t a;
    asm("{ .reg .u64 t; cvta.to.shared.u64 t, %1; cvt.u32.u64 %0, t; }" : "=r"(a) : "l"(p));
    return a;
}
#define CVT2(r, loe, hie) asm("cvt.rn.bf16x2.f32 %0, %1, %2;" : "=r"(r) : "f"(hie), "f"(loe))

#define LDSM4(r0, r1, r2, r3, a)                                               \
    asm volatile("ldmatrix.sync.aligned.m8n8.x4.shared.b16 {%0,%1,%2,%3}, [%4];" \
                 : "=r"(r0), "=r"(r1), "=r"(r2), "=r"(r3) : "r"(a))

#define MMA(c, a0, a1, a2, a3, b0, b1)                                         \
    asm volatile("mma.sync.aligned.m16n8k16.row.col.f32.bf16.bf16.f32 "        \
                 "{%0,%1,%2,%3},{%4,%5,%6,%7},{%8,%9},{%0,%1,%2,%3};"          \
                 : "+f"((c)[0]), "+f"((c)[1]), "+f"((c)[2]), "+f"((c)[3])      \
                 : "r"(a0), "r"(a1), "r"(a2), "r"(a3), "r"(b0), "r"(b1))

__device__ __forceinline__ void cp16(uint32_t dst, const void* src) {
    asm volatile("cp.async.ca.shared.global [%0], [%1], 16;" :: "r"(dst), "l"(src));
}
#define CP_COMMIT() asm volatile("cp.async.commit_group;" ::: "memory")
#define CP_WAIT(n)  asm volatile("cp.async.wait_group %0;" :: "n"(n) : "memory")

// ---------- prep: W [k][e] f32 -> Wt hi/lo bf16 [e][k], k-permuted (verified R7/R8) ----------
__global__ __launch_bounds__(256)
void prep_w_kernel(const float* __restrict__ W) {
    __shared__ float tile[32][65];
    const int t = threadIdx.x;
    const int k0 = blockIdx.x * 32;
    {
        int kr = t >> 3, e8 = (t & 7) * 8;
        float4 v0 = *(const float4*)&W[(size_t)(k0 + kr) * NEXP + e8];
        float4 v1 = *(const float4*)&W[(size_t)(k0 + kr) * NEXP + e8 + 4];
        tile[kr][e8 + 0] = v0.x; tile[kr][e8 + 1] = v0.y;
        tile[kr][e8 + 2] = v0.z; tile[kr][e8 + 3] = v0.w;
        tile[kr][e8 + 4] = v1.x; tile[kr][e8 + 5] = v1.y;
        tile[kr][e8 + 6] = v1.z; tile[kr][e8 + 7] = v1.w;
    }
    __syncthreads();
    {
        int e = t >> 2, part = t & 3;
        unsigned short hbuf[8], lbuf[8];
        #pragma unroll
        for (int i = 0; i < 8; ++i) {
            int p_local = part * 8 + i;
            int p16 = p_local & 15;
            int src_local = (p_local & 16) + 4 * ((p16 & 7) >> 1) + (p16 & 1)
                            + 2 * ((p16 >> 3) & 1);
            float w = tile[src_local][e];
            __nv_bfloat16 hb = __float2bfloat16(w);
            float lo = w - __bfloat162float(hb);
            hbuf[i] = __bfloat16_as_ushort(hb);
            lbuf[i] = __bfloat16_as_ushort(__float2bfloat16(lo));
        }
        size_t idx = (size_t)e * DIM + k0 + part * 8;
        *(uint4*)&g_WtHi[idx] = *(uint4*)hbuf;
        *(uint4*)&g_WtLo[idx] = *(uint4*)lbuf;
    }
}

// ---------- main: HMMA router, KC=128 3-stage, LDSM hoisted ----------
__global__ __launch_bounds__(256, 2)
void router_mma_kernel(const float* __restrict__ x,
                       const float* __restrict__ W,
                       const float* __restrict__ b,
                       float* __restrict__ out) {
    extern __shared__ char smem[];
    __shared__ float s_bias[NEXP];
    __shared__ float s_lg[NEXP];
    __shared__ int   s_fl[BM];
    __shared__ int   s_cnt;

    const uint32_t sb = smem_u32(smem);
    const int tid  = threadIdx.x;
    const int lane = tid & 31;
    const int wid  = tid >> 5;
    const int wq   = wid & 3;    // row group (16 rows)
    const int eh   = wid >> 2;   // expert half (32 experts)
    const int m0   = blockIdx.x * BM;

    if (tid < NEXP) s_bias[tid] = b[tid];
    if (tid == 0) s_cnt = 0;

    // B stage fill: per split 64 rows x 256B; thread covers 64B of its row
    const int frow = tid >> 2, fq = tid & 3;
    const char* wHRow = (const char*)(g_WtHi + (size_t)frow * DIM);
    const char* wLRow = (const char*)(g_WtLo + (size_t)frow * DIM);
    auto stage_fill = [&](int c, int s) {
        uint32_t dH = sb + OBH(s) + frow * BROWB + fq * 64;
        uint32_t dL = sb + OBL(s) + frow * BROWB + fq * 64;
        const char* sH = wHRow + (size_t)c * (KC * 2) + fq * 64;
        const char* sL = wLRow + (size_t)c * (KC * 2) + fq * 64;
        #pragma unroll
        for (int i = 0; i < 4; ++i) {
            cp16(dH + i * 16, sH + i * 16);
            cp16(dL + i * 16, sL + i * 16);
        }
    };

    // A: direct LDG.128; thread covers rows (r, r+8), physical cols t*16 + rq*4
    const int rr = lane >> 2;
    const int rq = lane & 3;
    const float* xpA = x + (size_t)(m0 + wq * 16 + rr) * DIM + rq * 4;
    const float* xpB = xpA + (size_t)8 * DIM;

    float acc[4][4];
    #pragma unroll
    for (int nf = 0; nf < 4; ++nf)
        #pragma unroll
        for (int q = 0; q < 4; ++q) acc[nf][q] = 0.0f;

    // B read addressing (ldmatrix)
    const int lnN = ((lane >> 4) & 1) * 8 + (lane & 7);
    const int lnK = ((lane >> 3) & 1) * 8;
    const uint32_t lmOff = (uint32_t)(eh * 32 * BROWB + lnN * BROWB + lnK * 2);

    // prologue: 2 B stages in flight, 4 j-steps of A in registers
    stage_fill(0, 0); CP_COMMIT();
    stage_fill(1, 1); CP_COMMIT();
    float4 fb[4], gb[4];
    #pragma unroll
    for (int j = 0; j < 4; ++j) {
        fb[j] = *(const float4*)(xpA + j * 16);
        gb[j] = *(const float4*)(xpB + j * 16);
    }

    for (int c = 0; c < NCHUNK; ++c) {
        CP_WAIT(1);
        __syncthreads();          // chunk c visible; chunk c-1 (stage (c+2)%3) consumed
        if (c + 2 < NCHUNK) stage_fill(c + 2, (c + 2) % 3);
        CP_COMMIT();

        const int s = c % 3;
        const uint32_t bHb = sb + OBH(s) + lmOff;
        const uint32_t bLb = sb + OBL(s) + lmOff;
        const bool pf = (c + 1 <= NCHUNK);   // t+4 valid while c*8+j+4 < 128

        #pragma unroll
        for (int j = 0; j < 8; ++j) {
            // 1) A register prefetch for step t+4 (slot (j+4)&3 == j&3)
            const float4 f = fb[j & 3];
            const float4 g = gb[j & 3];
            {
                const int t4 = c * 8 + j + 4;
                if (t4 < NCHUNK * 8) {
                    fb[j & 3] = *(const float4*)(xpA + t4 * 16);
                    gb[j & 3] = *(const float4*)(xpB + t4 * 16);
                }
            }

            // 2) LDSMs issued FIRST; converts below hide their latency
            uint32_t h0, h1, h2, h3, h4, h5, h6, h7;
            uint32_t l0, l1, l2, l3, l4, l5, l6, l7;
            LDSM4(h0, h1, h2, h3, bHb + j * 32);
            LDSM4(h4, h5, h6, h7, bHb + 16 * BROWB + j * 32);
            LDSM4(l0, l1, l2, l3, bLb + j * 32);
            LDSM4(l4, l5, l6, l7, bLb + 16 * BROWB + j * 32);

            // 3) A frags: bf16 hi + residual lo (permuted-B layout)
            uint32_t aH0, aH1, aH2, aH3, aL0, aL1, aL2, aL3;
            CVT2(aH0, f.x, f.y);
            CVT2(aH2, f.z, f.w);
            CVT2(aH1, g.x, g.y);
            CVT2(aH3, g.z, g.w);
            float e0, e1;
            e0 = f.x - __uint_as_float(aH0 << 16);
            e1 = f.y - __uint_as_float(aH0 & 0xffff0000u);
            CVT2(aL0, e0, e1);
            e0 = f.z - __uint_as_float(aH2 << 16);
            e1 = f.w - __uint_as_float(aH2 & 0xffff0000u);
            CVT2(aL2, e0, e1);
            e0 = g.x - __uint_as_float(aH1 << 16);
            e1 = g.y - __uint_as_float(aH1 & 0xffff0000u);
            CVT2(aL1, e0, e1);
            e0 = g.z - __uint_as_float(aH3 << 16);
            e1 = g.w - __uint_as_float(aH3 & 0xffff0000u);
            CVT2(aL3, e0, e1);

            // 4) 12 MMAs, round-robin over 4 accumulators
            MMA(acc[0], aH0, aH1, aH2, aH3, h0, h1);
            MMA(acc[1], aH0, aH1, aH2, aH3, h2, h3);
            MMA(acc[2], aH0, aH1, aH2, aH3, h4, h5);
            MMA(acc[3], aH0, aH1, aH2, aH3, h6, h7);
            MMA(acc[0], aH0, aH1, aH2, aH3, l0, l1);
            MMA(acc[1], aH0, aH1, aH2, aH3, l2, l3);
            MMA(acc[2], aH0, aH1, aH2, aH3, l4, l5);
            MMA(acc[3], aH0, aH1, aH2, aH3, l6, l7);
            MMA(acc[0], aL0, aL1, aL2, aL3, h0, h1);
            MMA(acc[1], aL0, aL1, aL2, aL3, h2, h3);
            MMA(acc[2], aL0, aL1, aL2, aL3, h4, h5);
            MMA(acc[3], aL0, aL1, aL2, aL3, h6, h7);
        }
        (void)pf;
    }

    // ---- epilogue: logits to smem overlay, per-token top-2 + softmax ----
    __syncthreads();
    float* ls = (float*)smem;
    {
        const int r  = wq * 16 + rr;
        const int cb = rq * 2;
        #pragma unroll
        for (int nf = 0; nf < 4; ++nf) {
            const int e0 = eh * 32 + nf * 8 + cb;
            ls[r * 65 + e0]           = acc[nf][0];
            ls[r * 65 + e0 + 1]       = acc[nf][1];
            ls[(r + 8) * 65 + e0]     = acc[nf][2];
            ls[(r + 8) * 65 + e0 + 1] = acc[nf][3];
        }
    }
    __syncthreads();

    if (tid < BM) {
        const float NEG = __int_as_float(0xff800000);
        float m1 = NEG, m2 = NEG, m3 = NEG;
        int i1 = 0, i2 = 0;
        #pragma unroll
        for (int e = 0; e < NEXP; ++e) {
            float v = ls[tid * 65 + e] + s_bias[e];
            if (v > m1)      { m3 = m2; m2 = m1; i2 = i1; m1 = v; i1 = e; }
            else if (v > m2) { m3 = m2; m2 = v; i2 = e; }
            else if (v > m3) { m3 = v; }
        }
        float ssum = 0.0f;
        #pragma unroll
        for (int e = 0; e < NEXP; ++e)
            ssum += expf(ls[tid * 65 + e] + s_bias[e] - m1);

        const int tok = m0 + tid;
        out[(size_t)tok * 2 + 0] = (float)i1;
        out[(size_t)tok * 2 + 1] = (float)i2;
        out[(size_t)2 * NTOK + tok * 2 + 0] = 1.0f / ssum;
        out[(size_t)2 * NTOK + tok * 2 + 1] = expf(m2 - m1) / ssum;

        if ((m1 - m2) < TAU || (m2 - m3) < TAU) {
            int ix = atomicAdd(&s_cnt, 1);
            s_fl[ix] = tid;
        }
    }
    __syncthreads();

    // ---- inline rescue: exact fp32 recompute for ambiguous tokens ----
    const int cnt = s_cnt;
    for (int i = 0; i < cnt; ++i) {
        const int tok = m0 + s_fl[i];
        const float* xr = x + (size_t)tok * DIM;
        const int e = tid >> 2, q = tid & 3;
        float s = 0.0f;
        const int k0 = q * (DIM / 4);
        for (int k = k0; k < k0 + DIM / 4; ++k)
            s = fmaf(xr[k], W[(size_t)k * NEXP + e], s);
        s += __shfl_xor_sync(0xffffffffu, s, 1);
        s += __shfl_xor_sync(0xffffffffu, s, 2);
        if (q == 0) s_lg[e] = s + s_bias[e];
        __syncthreads();

        if (tid == 0) {
            const float NEG = __int_as_float(0xff800000);
            float m1 = NEG, m2 = NEG;
            int i1 = 0, i2 = 0;
            for (int ee = 0; ee < NEXP; ++ee) {
                float v = s_lg[ee];
                if (v > m1)      { m2 = m1; i2 = i1; m1 = v; i1 = ee; }
                else if (v > m2) { m2 = v; i2 = ee; }
            }
            float ssum = 0.0f;
            for (int ee = 0; ee < NEXP; ++ee) ssum += expf(s_lg[ee] - m1);
            out[(size_t)tok * 2 + 0] = (float)i1;
            out[(size_t)tok * 2 + 1] = (float)i2;
            out[(size_t)2 * NTOK + tok * 2 + 0] = 1.0f / ssum;
            out[(size_t)2 * NTOK + tok * 2 + 1] = expf(m2 - m1) / ssum;
        }
        __syncthreads();
    }
}

extern "C" void kernel_launch(void* const* d_in, const int* in_sizes, int n_in,
                              void* d_out, int out_size) {
    const float* x = (const float*)d_in[0];
    const float* W = (const float*)d_in[1];
    const float* b = (const float*)d_in[2];
    float* out = (float*)d_out;

    cudaFuncSetAttribute(router_mma_kernel,
                         cudaFuncAttributeMaxDynamicSharedMemorySize, SMEM_SZ);

    prep_w_kernel<<<DIM / 32, 256>>>(W);
    router_mma_kernel<<<NTOK / BM, 256, SMEM_SZ>>>(x, W, b, out);
}

// round 16
// speedup vs baseline: 1.2876x; 1.2876x over previous
#include <cuda_runtime.h>
#include <cuda_bf16.h>
#include <cstdint>
#include <math.h>

#define DIM     2048
#define NEXP    64
#define NTOK    16384
#define BM      64
#define KC      64            // K per chunk
#define NCHUNK  (DIM / KC)    // 32
#define BROWB   144           // bf16 B row: 128B data + 16B pad
#define SPLIT_B 9216          // 64 rows * 144B
#define STAGE_B 18432         // hi + lo
#define OBH(s)  ((s) * STAGE_B)
#define OBL(s)  ((s) * STAGE_B + SPLIT_B)
#define SMEM_SZ (4 * STAGE_B) // 73728
#define TAU 1e-4f

__device__ unsigned short g_WtHi[NEXP * DIM];
__device__ unsigned short g_WtLo[NEXP * DIM];

// ---------- helpers ----------
__device__ __forceinline__ uint32_t smem_u32(const void* p) {
    uint32_t a;
    asm("{ .reg .u64 t; cvta.to.shared.u64 t, %1; cvt.u32.u64 %0, t; }" : "=r"(a) : "l"(p));
    return a;
}
#define CVT2(r, loe, hie) asm("cvt.rn.bf16x2.f32 %0, %1, %2;" : "=r"(r) : "f"(hie), "f"(loe))

#define LDSM4(r0, r1, r2, r3, a)                                               \
    asm volatile("ldmatrix.sync.aligned.m8n8.x4.shared.b16 {%0,%1,%2,%3}, [%4];" \
                 : "=r"(r0), "=r"(r1), "=r"(r2), "=r"(r3) : "r"(a))

#define MMA(c, a0, a1, a2, a3, b0, b1)                                         \
    asm volatile("mma.sync.aligned.m16n8k16.row.col.f32.bf16.bf16.f32 "        \
                 "{%0,%1,%2,%3},{%4,%5,%6,%7},{%8,%9},{%0,%1,%2,%3};"          \
                 : "+f"((c)[0]), "+f"((c)[1]), "+f"((c)[2]), "+f"((c)[3])      \
                 : "r"(a0), "r"(a1), "r"(a2), "r"(a3), "r"(b0), "r"(b1))

__device__ __forceinline__ void cp16(uint32_t dst, const void* src) {
    asm volatile("cp.async.ca.shared.global [%0], [%1], 16;" :: "r"(dst), "l"(src));
}
#define CP_COMMIT() asm volatile("cp.async.commit_group;" ::: "memory")
#define CP_WAIT(n)  asm volatile("cp.async.wait_group %0;" :: "n"(n) : "memory")

// ---------- prep: W [k][e] f32 -> Wt hi/lo bf16 [e][k], k-permuted (verified R7/R8) ----------
__global__ __launch_bounds__(256)
void prep_w_kernel(const float* __restrict__ W) {
    __shared__ float tile[32][65];
    const int t = threadIdx.x;
    const int k0 = blockIdx.x * 32;
    {
        int kr = t >> 3, e8 = (t & 7) * 8;
        float4 v0 = *(const float4*)&W[(size_t)(k0 + kr) * NEXP + e8];
        float4 v1 = *(const float4*)&W[(size_t)(k0 + kr) * NEXP + e8 + 4];
        tile[kr][e8 + 0] = v0.x; tile[kr][e8 + 1] = v0.y;
        tile[kr][e8 + 2] = v0.z; tile[kr][e8 + 3] = v0.w;
        tile[kr][e8 + 4] = v1.x; tile[kr][e8 + 5] = v1.y;
        tile[kr][e8 + 6] = v1.z; tile[kr][e8 + 7] = v1.w;
    }
    __syncthreads();
    {
        int e = t >> 2, part = t & 3;
        unsigned short hbuf[8], lbuf[8];
        #pragma unroll
        for (int i = 0; i < 8; ++i) {
            int p_local = part * 8 + i;
            int p16 = p_local & 15;
            int src_local = (p_local & 16) + 4 * ((p16 & 7) >> 1) + (p16 & 1)
                            + 2 * ((p16 >> 3) & 1);
            float w = tile[src_local][e];
            __nv_bfloat16 hb = __float2bfloat16(w);
            float lo = w - __bfloat162float(hb);
            hbuf[i] = __bfloat16_as_ushort(hb);
            lbuf[i] = __bfloat16_as_ushort(__float2bfloat16(lo));
        }
        size_t idx = (size_t)e * DIM + k0 + part * 8;
        *(uint4*)&g_WtHi[idx] = *(uint4*)hbuf;
        *(uint4*)&g_WtLo[idx] = *(uint4*)lbuf;
    }
}

// ---------- main: R8 HMMA router, only change: LDSM issued first in j-body ----------
__global__ __launch_bounds__(256, 2)
void router_mma_kernel(const float* __restrict__ x,
                       const float* __restrict__ W,
                       const float* __restrict__ b,
                       float* __restrict__ out) {
    extern __shared__ char smem[];
    __shared__ float s_bias[NEXP];
    __shared__ float s_lg[NEXP];
    __shared__ int   s_fl[BM];
    __shared__ int   s_cnt;

    const uint32_t sb = smem_u32(smem);
    const int tid  = threadIdx.x;
    const int lane = tid & 31;
    const int wid  = tid >> 5;
    const int wq   = wid & 3;    // row group (16 rows)
    const int eh   = wid >> 2;   // expert half (32 experts)
    const int m0   = blockIdx.x * BM;

    if (tid < NEXP) s_bias[tid] = b[tid];
    if (tid == 0) s_cnt = 0;

    // B stage fill: per split 64 rows x 128B; thread covers 32B of its row
    const int frow = tid >> 2, fq = tid & 3;
    const char* wHRow = (const char*)(g_WtHi + (size_t)frow * DIM);
    const char* wLRow = (const char*)(g_WtLo + (size_t)frow * DIM);
    auto stage_fill = [&](int c, int s) {
        uint32_t dH = sb + OBH(s) + frow * BROWB + fq * 32;
        uint32_t dL = sb + OBL(s) + frow * BROWB + fq * 32;
        const char* sH = wHRow + (size_t)c * (KC * 2) + fq * 32;
        const char* sL = wLRow + (size_t)c * (KC * 2) + fq * 32;
        cp16(dH,      sH);
        cp16(dH + 16, sH + 16);
        cp16(dL,      sL);
        cp16(dL + 16, sL + 16);
    };

    // A: direct LDG.128; thread covers rows (r, r+8), physical cols t*16 + rq*4
    const int rr = lane >> 2;
    const int rq = lane & 3;
    const float* xpA = x + (size_t)(m0 + wq * 16 + rr) * DIM + rq * 4;
    const float* xpB = xpA + (size_t)8 * DIM;

    float acc[4][4];
    #pragma unroll
    for (int nf = 0; nf < 4; ++nf)
        #pragma unroll
        for (int q = 0; q < 4; ++q) acc[nf][q] = 0.0f;

    // B read addressing (ldmatrix)
    const int lnN = ((lane >> 4) & 1) * 8 + (lane & 7);
    const int lnK = ((lane >> 3) & 1) * 8;
    const uint32_t lmOff = (uint32_t)(eh * 32 * BROWB + lnN * BROWB + lnK * 2);

    // prologue: 3 B stages in flight, full chunk (4 j-steps) of A in registers
    stage_fill(0, 0); CP_COMMIT();
    stage_fill(1, 1); CP_COMMIT();
    stage_fill(2, 2); CP_COMMIT();
    float4 fb[4], gb[4];
    #pragma unroll
    for (int j = 0; j < 4; ++j) {
        fb[j] = *(const float4*)(xpA + j * 16);
        gb[j] = *(const float4*)(xpB + j * 16);
    }

    for (int c = 0; c < NCHUNK; ++c) {
        CP_WAIT(2);
        __syncthreads();          // chunk c visible; all warps done with stage (c-1)&3
        if (c + 3 < NCHUNK) stage_fill(c + 3, (c + 3) & 3);
        CP_COMMIT();

        const int s = c & 3;
        const uint32_t bHb = sb + OBH(s) + lmOff;
        const uint32_t bLb = sb + OBL(s) + lmOff;
        const bool pf = (c + 1 < NCHUNK);

        #pragma unroll
        for (int j = 0; j < 4; ++j) {
            // 1) LDSMs FIRST — the A prefetch + convert block below covers LDS latency
            uint32_t h0, h1, h2, h3, h4, h5, h6, h7;
            uint32_t l0, l1, l2, l3, l4, l5, l6, l7;
            LDSM4(h0, h1, h2, h3, bHb + j * 32);
            LDSM4(h4, h5, h6, h7, bHb + 16 * BROWB + j * 32);
            LDSM4(l0, l1, l2, l3, bLb + j * 32);
            LDSM4(l4, l5, l6, l7, bLb + 16 * BROWB + j * 32);

            // 2) A register prefetch: step t+4 (next chunk, same j slot)
            const float4 f = fb[j];
            const float4 g = gb[j];
            if (pf) {
                const int t4 = (c + 1) * 4 + j;
                fb[j] = *(const float4*)(xpA + t4 * 16);
                gb[j] = *(const float4*)(xpB + t4 * 16);
            }

            // 3) A frags: bf16 hi + residual lo (permuted-B layout)
            uint32_t aH0, aH1, aH2, aH3, aL0, aL1, aL2, aL3;
            CVT2(aH0, f.x, f.y);
            CVT2(aH2, f.z, f.w);
            CVT2(aH1, g.x, g.y);
            CVT2(aH3, g.z, g.w);
            float e0, e1;
            e0 = f.x - __uint_as_float(aH0 << 16);
            e1 = f.y - __uint_as_float(aH0 & 0xffff0000u);
            CVT2(aL0, e0, e1);
            e0 = f.z - __uint_as_float(aH2 << 16);
            e1 = f.w - __uint_as_float(aH2 & 0xffff0000u);
            CVT2(aL2, e0, e1);
            e0 = g.x - __uint_as_float(aH1 << 16);
            e1 = g.y - __uint_as_float(aH1 & 0xffff0000u);
            CVT2(aL1, e0, e1);
            e0 = g.z - __uint_as_float(aH3 << 16);
            e1 = g.w - __uint_as_float(aH3 & 0xffff0000u);
            CVT2(aL3, e0, e1);

            // 4) 12 MMAs, round-robin over 4 accumulators
            MMA(acc[0], aH0, aH1, aH2, aH3, h0, h1);
            MMA(acc[1], aH0, aH1, aH2, aH3, h2, h3);
            MMA(acc[2], aH0, aH1, aH2, aH3, h4, h5);
            MMA(acc[3], aH0, aH1, aH2, aH3, h6, h7);
            MMA(acc[0], aH0, aH1, aH2, aH3, l0, l1);
            MMA(acc[1], aH0, aH1, aH2, aH3, l2, l3);
            MMA(acc[2], aH0, aH1, aH2, aH3, l4, l5);
            MMA(acc[3], aH0, aH1, aH2, aH3, l6, l7);
            MMA(acc[0], aL0, aL1, aL2, aL3, h0, h1);
            MMA(acc[1], aL0, aL1, aL2, aL3, h2, h3);
            MMA(acc[2], aL0, aL1, aL2, aL3, h4, h5);
            MMA(acc[3], aL0, aL1, aL2, aL3, h6, h7);
        }
    }

    // ---- epilogue: logits to smem overlay, per-token top-2 + softmax ----
    __syncthreads();
    float* ls = (float*)smem;
    {
        const int r  = wq * 16 + rr;
        const int cb = rq * 2;
        #pragma unroll
        for (int nf = 0; nf < 4; ++nf) {
            const int e0 = eh * 32 + nf * 8 + cb;
            ls[r * 65 + e0]           = acc[nf][0];
            ls[r * 65 + e0 + 1]       = acc[nf][1];
            ls[(r + 8) * 65 + e0]     = acc[nf][2];
            ls[(r + 8) * 65 + e0 + 1] = acc[nf][3];
        }
    }
    __syncthreads();

    if (tid < BM) {
        const float NEG = __int_as_float(0xff800000);
        float m1 = NEG, m2 = NEG, m3 = NEG;
        int i1 = 0, i2 = 0;
        #pragma unroll
        for (int e = 0; e < NEXP; ++e) {
            float v = ls[tid * 65 + e] + s_bias[e];
            if (v > m1)      { m3 = m2; m2 = m1; i2 = i1; m1 = v; i1 = e; }
            else if (v > m2) { m3 = m2; m2 = v; i2 = e; }
            else if (v > m3) { m3 = v; }
        }
        float ssum = 0.0f;
        #pragma unroll
        for (int e = 0; e < NEXP; ++e)
            ssum += expf(ls[tid * 65 + e] + s_bias[e] - m1);

        const int tok = m0 + tid;
        out[(size_t)tok * 2 + 0] = (float)i1;
        out[(size_t)tok * 2 + 1] = (float)i2;
        out[(size_t)2 * NTOK + tok * 2 + 0] = 1.0f / ssum;
        out[(size_t)2 * NTOK + tok * 2 + 1] = expf(m2 - m1) / ssum;

        if ((m1 - m2) < TAU || (m2 - m3) < TAU) {
            int ix = atomicAdd(&s_cnt, 1);
            s_fl[ix] = tid;
        }
    }
    __syncthreads();

    // ---- inline rescue: exact fp32 recompute for ambiguous tokens ----
    const int cnt = s_cnt;
    for (int i = 0; i < cnt; ++i) {
        const int tok = m0 + s_fl[i];
        const float* xr = x + (size_t)tok * DIM;
        const int e = tid >> 2, q = tid & 3;
        float s = 0.0f;
        const int k0 = q * (DIM / 4);
        for (int k = k0; k < k0 + DIM / 4; ++k)
            s = fmaf(xr[k], W[(size_t)k * NEXP + e], s);
        s += __shfl_xor_sync(0xffffffffu, s, 1);
        s += __shfl_xor_sync(0xffffffffu, s, 2);
        if (q == 0) s_lg[e] = s + s_bias[e];
        __syncthreads();

        if (tid == 0) {
            const float NEG = __int_as_float(0xff800000);
            float m1 = NEG, m2 = NEG;
            int i1 = 0, i2 = 0;
            for (int ee = 0; ee < NEXP; ++ee) {
                float v = s_lg[ee];
                if (v > m1)      { m2 = m1; i2 = i1; m1 = v; i1 = ee; }
                else if (v > m2) { m2 = v; i2 = ee; }
            }
            float ssum = 0.0f;
            for (int ee = 0; ee < NEXP; ++ee) ssum += expf(s_lg[ee] - m1);
            out[(size_t)tok * 2 + 0] = (float)i1;
            out[(size_t)tok * 2 + 1] = (float)i2;
            out[(size_t)2 * NTOK + tok * 2 + 0] = 1.0f / ssum;
            out[(size_t)2 * NTOK + tok * 2 + 1] = expf(m2 - m1) / ssum;
        }
        __syncthreads();
    }
}

extern "C" void kernel_launch(void* const* d_in, const int* in_sizes, int n_in,
                              void* d_out, int out_size) {
    const float* x = (const float*)d_in[0];
    const float* W = (const float*)d_in[1];
    const float* b = (const float*)d_in[2];
    float* out = (float*)d_out;

    cudaFuncSetAttribute(router_mma_kernel,
                         cudaFuncAttributeMaxDynamicSharedMemorySize, SMEM_SZ);

    prep_w_kernel<<<DIM / 32, 256>>>(W);
    router_mma_kernel<<<NTOK / BM, 256, SMEM_SZ>>>(x, W, b, out);
}

// round 17
// speedup vs baseline: 1.3751x; 1.0680x over previous
#include <cuda_runtime.h>
#include <cuda_bf16.h>
#include <cstdint>
#include <math.h>

#define DIM     2048
#define NEXP    64
#define NTOK    16384
#define BM      64
#define NSTEP   (DIM / 16)    // 128 k16 steps
#define TAU 1e-4f

// B in MMA-fragment order: [t(128)][eh(2)][g(2)][sp(2)][lane(32)] x 16B
__device__ uint4 g_Wf[NSTEP * 2 * 2 * 2 * 32];

// ---------- helpers ----------
#define CVT2(r, loe, hie) asm("cvt.rn.bf16x2.f32 %0, %1, %2;" : "=r"(r) : "f"(hie), "f"(loe))

#define MMA(c, a0, a1, a2, a3, b0, b1)                                         \
    asm volatile("mma.sync.aligned.m16n8k16.row.col.f32.bf16.bf16.f32 "        \
                 "{%0,%1,%2,%3},{%4,%5,%6,%7},{%8,%9},{%0,%1,%2,%3};"          \
                 : "+f"((c)[0]), "+f"((c)[1]), "+f"((c)[2]), "+f"((c)[3])      \
                 : "r"(a0), "r"(a1), "r"(a2), "r"(a3), "r"(b0), "r"(b1))

// verified k-permutation (R7/R8): logical frag pos -> physical k within 16
__device__ __forceinline__ int perm16(int p) {
    return 4 * ((p & 7) >> 1) + (p & 1) + 2 * ((p >> 3) & 1);
}

// ---------- prep: W [k][e] f32 -> fragment-ordered bf16 hi/lo ----------
__global__ __launch_bounds__(256)
void prep_w_kernel(const float* __restrict__ W) {
    const int idx  = blockIdx.x * 256 + threadIdx.x;   // 0..32767
    const int lane = idx & 31;
    const int sp   = (idx >> 5) & 1;
    const int g    = (idx >> 6) & 1;
    const int eh   = (idx >> 7) & 1;
    const int t    = idx >> 8;                          // 0..127

    uint32_t regs[4];
    #pragma unroll
    for (int v = 0; v < 4; ++v) {
        const int tile = v >> 1, r = v & 1;
        const int n  = eh * 32 + g * 16 + tile * 8 + (lane >> 2);
        const int p0 = (lane & 3) * 2 + r * 8;          // even logical pos
        const int k  = t * 16 + perm16(p0);             // physical (pk+1 adjacent)
        const float w0 = W[(size_t)k * NEXP + n];
        const float w1 = W[(size_t)(k + 1) * NEXP + n];
        unsigned short b0, b1;
        if (sp == 0) {
            b0 = __bfloat16_as_ushort(__float2bfloat16(w0));
            b1 = __bfloat16_as_ushort(__float2bfloat16(w1));
        } else {
            float h0 = __bfloat162float(__float2bfloat16(w0));
            float h1 = __bfloat162float(__float2bfloat16(w1));
            b0 = __bfloat16_as_ushort(__float2bfloat16(w0 - h0));
            b1 = __bfloat16_as_ushort(__float2bfloat16(w1 - h1));
        }
        regs[v] = (uint32_t)b0 | ((uint32_t)b1 << 16);  // low = even k (matches A pack)
    }
    g_Wf[idx] = make_uint4(regs[0], regs[1], regs[2], regs[3]);
}

// ---------- main: HMMA router, B direct from L2 (no smem pipeline) ----------
__global__ __launch_bounds__(256, 2)
void router_mma_kernel(const float* __restrict__ x,
                       const float* __restrict__ W,
                       const float* __restrict__ b,
                       float* __restrict__ out) {
    __shared__ float ls[BM * 65];
    __shared__ float s_bias[NEXP];
    __shared__ float s_lg[NEXP];
    __shared__ int   s_fl[BM];
    __shared__ int   s_cnt;

    const int tid  = threadIdx.x;
    const int lane = tid & 31;
    const int wid  = tid >> 5;
    const int wq   = wid & 3;    // row group (16 rows)
    const int eh   = wid >> 2;   // expert half (32 experts)
    const int m0   = blockIdx.x * BM;

    if (tid < NEXP) s_bias[tid] = b[tid];
    if (tid == 0) s_cnt = 0;

    // A: direct LDG.128; thread covers rows (r, r+8), physical cols t*16 + rq*4
    const int rr = lane >> 2;
    const int rq = lane & 3;
    const float* xpA = x + (size_t)(m0 + wq * 16 + rr) * DIM + rq * 4;
    const float* xpB = xpA + (size_t)8 * DIM;

    // B: fragment-ordered gmem, per warp: base + t*4096
    const char* wB = (const char*)g_Wf + eh * 2048 + lane * 16;

    float acc[4][4];
    #pragma unroll
    for (int nf = 0; nf < 4; ++nf)
        #pragma unroll
        for (int q = 0; q < 4; ++q) acc[nf][q] = 0.0f;

    // prologue: A depth-4 register prefetch, B depth-2 register ring
    float4 fb[4], gb[4];
    #pragma unroll
    for (int j = 0; j < 4; ++j) {
        fb[j] = *(const float4*)(xpA + j * 16);
        gb[j] = *(const float4*)(xpB + j * 16);
    }
    uint4 bH0[2], bL0[2], bH1[2], bL1[2];
    #pragma unroll
    for (int s = 0; s < 2; ++s) {
        const char* p = wB + (size_t)s * 4096;
        bH0[s] = *(const uint4*)(p);
        bL0[s] = *(const uint4*)(p + 512);
        bH1[s] = *(const uint4*)(p + 1024);
        bL1[s] = *(const uint4*)(p + 1536);
    }

    for (int c = 0; c < NSTEP / 4; ++c) {
        #pragma unroll
        for (int j = 0; j < 4; ++j) {
            const int t = c * 4 + j;

            // consume B ring slot (t&1 == j&1)
            const uint4 H0 = bH0[j & 1];
            const uint4 L0 = bL0[j & 1];
            const uint4 H1 = bH1[j & 1];
            const uint4 L1 = bL1[j & 1];
            // B prefetch t+2 into same slot
            if (t + 2 < NSTEP) {
                const char* p = wB + (size_t)(t + 2) * 4096;
                bH0[j & 1] = *(const uint4*)(p);
                bL0[j & 1] = *(const uint4*)(p + 512);
                bH1[j & 1] = *(const uint4*)(p + 1024);
                bL1[j & 1] = *(const uint4*)(p + 1536);
            }

            // A register prefetch t+4 (same j slot)
            const float4 f = fb[j];
            const float4 g = gb[j];
            if (t + 4 < NSTEP) {
                fb[j] = *(const float4*)(xpA + (t + 4) * 16);
                gb[j] = *(const float4*)(xpB + (t + 4) * 16);
            }

            // A frags: bf16 hi + residual lo (permuted-B layout, verified)
            uint32_t aH0, aH1, aH2, aH3, aL0, aL1, aL2, aL3;
            CVT2(aH0, f.x, f.y);
            CVT2(aH2, f.z, f.w);
            CVT2(aH1, g.x, g.y);
            CVT2(aH3, g.z, g.w);
            float e0, e1;
            e0 = f.x - __uint_as_float(aH0 << 16);
            e1 = f.y - __uint_as_float(aH0 & 0xffff0000u);
            CVT2(aL0, e0, e1);
            e0 = f.z - __uint_as_float(aH2 << 16);
            e1 = f.w - __uint_as_float(aH2 & 0xffff0000u);
            CVT2(aL2, e0, e1);
            e0 = g.x - __uint_as_float(aH1 << 16);
            e1 = g.y - __uint_as_float(aH1 & 0xffff0000u);
            CVT2(aL1, e0, e1);
            e0 = g.z - __uint_as_float(aH3 << 16);
            e1 = g.w - __uint_as_float(aH3 & 0xffff0000u);
            CVT2(aL3, e0, e1);

            // 12 MMAs, round-robin over 4 accumulators (wiring identical to R16)
            MMA(acc[0], aH0, aH1, aH2, aH3, H0.x, H0.y);
            MMA(acc[1], aH0, aH1, aH2, aH3, H0.z, H0.w);
            MMA(acc[2], aH0, aH1, aH2, aH3, H1.x, H1.y);
            MMA(acc[3], aH0, aH1, aH2, aH3, H1.z, H1.w);
            MMA(acc[0], aH0, aH1, aH2, aH3, L0.x, L0.y);
            MMA(acc[1], aH0, aH1, aH2, aH3, L0.z, L0.w);
            MMA(acc[2], aH0, aH1, aH2, aH3, L1.x, L1.y);
            MMA(acc[3], aH0, aH1, aH2, aH3, L1.z, L1.w);
            MMA(acc[0], aL0, aL1, aL2, aL3, H0.x, H0.y);
            MMA(acc[1], aL0, aL1, aL2, aL3, H0.z, H0.w);
            MMA(acc[2], aL0, aL1, aL2, aL3, H1.x, H1.y);
            MMA(acc[3], aL0, aL1, aL2, aL3, H1.z, H1.w);
        }
    }

    // ---- epilogue: logits to smem, per-token top-2 + softmax (R8-verbatim) ----
    {
        const int r  = wq * 16 + rr;
        const int cb = rq * 2;
        #pragma unroll
        for (int nf = 0; nf < 4; ++nf) {
            const int e0 = eh * 32 + nf * 8 + cb;
            ls[r * 65 + e0]           = acc[nf][0];
            ls[r * 65 + e0 + 1]       = acc[nf][1];
            ls[(r + 8) * 65 + e0]     = acc[nf][2];
            ls[(r + 8) * 65 + e0 + 1] = acc[nf][3];
        }
    }
    __syncthreads();

    if (tid < BM) {
        const float NEG = __int_as_float(0xff800000);
        float m1 = NEG, m2 = NEG, m3 = NEG;
        int i1 = 0, i2 = 0;
        #pragma unroll
        for (int e = 0; e < NEXP; ++e) {
            float v = ls[tid * 65 + e] + s_bias[e];
            if (v > m1)      { m3 = m2; m2 = m1; i2 = i1; m1 = v; i1 = e; }
            else if (v > m2) { m3 = m2; m2 = v; i2 = e; }
            else if (v > m3) { m3 = v; }
        }
        float ssum = 0.0f;
        #pragma unroll
        for (int e = 0; e < NEXP; ++e)
            ssum += expf(ls[tid * 65 + e] + s_bias[e] - m1);

        const int tok = m0 + tid;
        out[(size_t)tok * 2 + 0] = (float)i1;
        out[(size_t)tok * 2 + 1] = (float)i2;
        out[(size_t)2 * NTOK + tok * 2 + 0] = 1.0f / ssum;
        out[(size_t)2 * NTOK + tok * 2 + 1] = expf(m2 - m1) / ssum;

        if ((m1 - m2) < TAU || (m2 - m3) < TAU) {
            int ix = atomicAdd(&s_cnt, 1);
            s_fl[ix] = tid;
        }
    }
    __syncthreads();

    // ---- inline rescue: exact fp32 recompute for ambiguous tokens ----
    const int cnt = s_cnt;
    for (int i = 0; i < cnt; ++i) {
        const int tok = m0 + s_fl[i];
        const float* xr = x + (size_t)tok * DIM;
        const int e = tid >> 2, q = tid & 3;
        float s = 0.0f;
        const int k0 = q * (DIM / 4);
        for (int k = k0; k < k0 + DIM / 4; ++k)
            s = fmaf(xr[k], W[(size_t)k * NEXP + e], s);
        s += __shfl_xor_sync(0xffffffffu, s, 1);
        s += __shfl_xor_sync(0xffffffffu, s, 2);
        if (q == 0) s_lg[e] = s + s_bias[e];
        __syncthreads();

        if (tid == 0) {
            const float NEG = __int_as_float(0xff800000);
            float m1 = NEG, m2 = NEG;
            int i1 = 0, i2 = 0;
            for (int ee = 0; ee < NEXP; ++ee) {
                float v = s_lg[ee];
                if (v > m1)      { m2 = m1; i2 = i1; m1 = v; i1 = ee; }
                else if (v > m2) { m2 = v; i2 = ee; }
            }
            float ssum = 0.0f;
            for (int ee = 0; ee < NEXP; ++ee) ssum += expf(s_lg[ee] - m1);
            out[(size_t)tok * 2 + 0] = (float)i1;
            out[(size_t)tok * 2 + 1] = (float)i2;
            out[(size_t)2 * NTOK + tok * 2 + 0] = 1.0f / ssum;
            out[(size_t)2 * NTOK + tok * 2 + 1] = expf(m2 - m1) / ssum;
        }
        __syncthreads();
    }
}

extern "C" void kernel_launch(void* const* d_in, const int* in_sizes, int n_in,
                              void* d_out, int out_size) {
    const float* x = (const float*)d_in[0];
    const float* W = (const float*)d_in[1];
    const float* b = (const float*)d_in[2];
    float* out = (float*)d_out;

    prep_w_kernel<<<128, 256>>>(W);
    router_mma_kernel<<<NTOK / BM, 256>>>(x, W, b, out);
}